// round 15
// baseline (speedup 1.0000x reference)
#include <cuda_runtime.h>
#include <cuda_fp16.h>
#include <math.h>
#include <stdint.h>

// ---------------------------------------------------------------------------
// Problem constants
// ---------------------------------------------------------------------------
#define B_   64
#define P_   225
#define K_   16
#define D_   640
#define MQ   (B_ * P_)      // 14400 query rows
#define NR   (K_ * P_)      // 3600 reference rows
#define NT2  29             // n tiles of 128
#define NRP  (NT2 * 128)    // 3712 padded reference rows

// GEMM tiling: BM=64, BN=128, BK=64; 8 warps (2m x 4n), warp tile 32x32
#define BM 64
#define BN 128
#define BK 64
#define LDA 648             // A smem row stride (fp16); row stride = 4 banks
#define NSTRIPE 4
#define NSTAGE 2
#define B_STAGE_BYTES (BN * 128)                    // 16384 (swizzled, no pad)

#define A_SMEM_BYTES (BM * LDA * 2)                 // 82944
#define SMEM_BYTES   (A_SMEM_BYTES + NSTAGE * B_STAGE_BYTES)  // 115712

// prep: 16 rows per 512-thread block (warp per row) + adapter tail blocks
#define ROWBLKS ((MQ + NRP) / 16)                   // 1132
#define ADPT_BLKS 20
#define PREP_BLOCKS (ROWBLKS + ADPT_BLKS)

// ---------------------------------------------------------------------------
// Scratch (allocation-free: __device__ globals)
// ---------------------------------------------------------------------------
__device__ __half g_qh[MQ * D_];
__device__ __half g_rh[NRP * D_];
__device__ float g_qnorm[MQ];
__device__ float g_pmax[NSTRIPE * MQ];
__device__ float g_h1p[5][K_ * 160];
__device__ float g_famean[D_];
__device__ float g_sref[B_];

// ---------------------------------------------------------------------------
// helpers
// ---------------------------------------------------------------------------
__device__ __forceinline__ uint32_t smem_u32(const void* p) {
    uint32_t a;
    asm("{ .reg .u64 t; cvta.to.shared.u64 t, %1; cvt.u32.u64 %0, t; }"
        : "=r"(a) : "l"(p));
    return a;
}
__device__ __forceinline__ void cp_async16(uint32_t dst, const void* src) {
    asm volatile("cp.async.cg.shared.global [%0], [%1], 16;"
                 :: "r"(dst), "l"(src) : "memory");
}
#define CP_COMMIT() asm volatile("cp.async.commit_group;" ::: "memory")
#define CP_WAIT0()  asm volatile("cp.async.wait_group 0;" ::: "memory")

__device__ __forceinline__ void ldsm_x4(uint32_t r[4], uint32_t addr) {
    asm volatile("ldmatrix.sync.aligned.m8n8.x4.shared.b16 {%0,%1,%2,%3}, [%4];"
                 : "=r"(r[0]), "=r"(r[1]), "=r"(r[2]), "=r"(r[3]) : "r"(addr));
}
__device__ __forceinline__ void mma16816(float c[4], const uint32_t a[4],
                                         const uint32_t b[2]) {
    asm volatile(
        "mma.sync.aligned.m16n8k16.row.col.f32.f16.f16.f32 "
        "{%0,%1,%2,%3}, {%4,%5,%6,%7}, {%8,%9}, {%0,%1,%2,%3};\n"
        : "+f"(c[0]), "+f"(c[1]), "+f"(c[2]), "+f"(c[3])
        : "r"(a[0]), "r"(a[1]), "r"(a[2]), "r"(a[3]), "r"(b[0]), "r"(b[1]));
}

// ---------------------------------------------------------------------------
// Kernel 1 (fused prep): warp-per-row q/r prep + adapter hidden partials
// ---------------------------------------------------------------------------
__global__ __launch_bounds__(512)
void mega_prep_kernel(const float* __restrict__ q_patch,
                      const float* __restrict__ r_patch,
                      const float* __restrict__ r_img,
                      const float* __restrict__ w1) {
    const int t = threadIdx.x;

    if (blockIdx.x < ROWBLKS) {
        const int lane = t & 31;
        const int row = blockIdx.x * 16 + (t >> 5);
        if (row < MQ) {
            const float4* x4 = (const float4*)(q_patch + (size_t)row * D_);
            __half* o = g_qh + (size_t)row * D_;
            float4 v[5];
            float ss = 0.f;
            #pragma unroll
            for (int j = 0; j < 5; ++j) {
                const int i4 = lane + 32 * j;
                v[j] = x4[i4];
                ss = fmaf(v[j].x, v[j].x, ss);
                ss = fmaf(v[j].y, v[j].y, ss);
                ss = fmaf(v[j].z, v[j].z, ss);
                ss = fmaf(v[j].w, v[j].w, ss);
                *(__half2*)(o + i4 * 4)     = __floats2half2_rn(v[j].x, v[j].y);
                *(__half2*)(o + i4 * 4 + 2) = __floats2half2_rn(v[j].z, v[j].w);
            }
            #pragma unroll
            for (int of = 16; of > 0; of >>= 1)
                ss += __shfl_xor_sync(0xffffffffu, ss, of);
            if (lane == 0) g_qnorm[row] = sqrtf(ss);
        } else {
            const int r = row - MQ;
            __half* o = g_rh + (size_t)r * D_;
            if (r >= NR) {
                #pragma unroll
                for (int j = 0; j < 5; ++j) {
                    const int i4 = lane + 32 * j;
                    *(__half2*)(o + i4 * 4)     = __floats2half2_rn(0.f, 0.f);
                    *(__half2*)(o + i4 * 4 + 2) = __floats2half2_rn(0.f, 0.f);
                }
            } else {
                const float4* x4 = (const float4*)(r_patch + (size_t)r * D_);
                float4 v[5];
                float ss = 0.f;
                #pragma unroll
                for (int j = 0; j < 5; ++j) {
                    v[j] = x4[lane + 32 * j];
                    ss = fmaf(v[j].x, v[j].x, ss);
                    ss = fmaf(v[j].y, v[j].y, ss);
                    ss = fmaf(v[j].z, v[j].z, ss);
                    ss = fmaf(v[j].w, v[j].w, ss);
                }
                #pragma unroll
                for (int of = 16; of > 0; of >>= 1)
                    ss += __shfl_xor_sync(0xffffffffu, ss, of);
                const float sc = 1.f / (sqrtf(ss) + 1e-6f);
                #pragma unroll
                for (int j = 0; j < 5; ++j) {
                    const int i4 = lane + 32 * j;
                    *(__half2*)(o + i4 * 4) =
                        __floats2half2_rn(v[j].x * sc, v[j].y * sc);
                    *(__half2*)(o + i4 * 4 + 2) =
                        __floats2half2_rn(v[j].z * sc, v[j].w * sc);
                }
            }
        }
    } else {
        const int grp = t >> 7;
        const int tg = t & 127;
        const int idx = (blockIdx.x - ROWBLKS) * 4 + grp;
        const int k = idx / 5, dc = idx % 5;
        __shared__ float axr[4][128];
        axr[grp][tg] = r_img[k * D_ + dc * 128 + tg];
        __syncthreads();
        const float* xr = axr[grp];
        #pragma unroll
        for (int rep = 0; rep < 2; ++rep) {
            const int i = tg + rep * 128;
            if (i < 160) {
                float s0 = 0.f, s1 = 0.f;
                const float* w = w1 + (size_t)(dc * 128) * 160 + i;
                #pragma unroll 8
                for (int d = 0; d < 128; d += 2) {
                    s0 = fmaf(xr[d], w[(size_t)d * 160], s0);
                    s1 = fmaf(xr[d + 1], w[(size_t)(d + 1) * 160], s1);
                }
                g_h1p[dc][k * 160 + i] = s0 + s1;
            }
        }
    }
}

// ---------------------------------------------------------------------------
// Kernel 2: adapter finish
// ---------------------------------------------------------------------------
__global__ void adapter_final_kernel(const float* __restrict__ w2) {
    __shared__ float h1s[K_ * 160];
    for (int idx = threadIdx.x; idx < K_ * 160; idx += 128) {
        float s = g_h1p[0][idx] + g_h1p[1][idx] + g_h1p[2][idx] +
                  g_h1p[3][idx] + g_h1p[4][idx];
        h1s[idx] = fmaxf(s, 0.f);
    }
    __syncthreads();
    const int j = blockIdx.x * 128 + threadIdx.x;
    float accm = 0.f;
    for (int k = 0; k < K_; ++k) {
        float s0 = 0.f, s1 = 0.f;
        const float* h = h1s + k * 160;
        #pragma unroll 4
        for (int i = 0; i < 160; i += 2) {
            s0 = fmaf(h[i], w2[i * D_ + j], s0);
            s1 = fmaf(h[i + 1], w2[(i + 1) * D_ + j], s1);
        }
        accm += fmaxf(s0 + s1, 0.f);
    }
    g_famean[j] = accm * (1.f / (float)K_);
}

// ---------------------------------------------------------------------------
// Kernel 3: tensor-core GEMM + row max. BN=128, swizzled B, ldsm_x4 B frags.
// ---------------------------------------------------------------------------
__global__ __launch_bounds__(256, 2)
void gemm_max_kernel() {
    extern __shared__ __align__(16) char smem[];
    __half* As = (__half*)smem;
    char* Bs = smem + A_SMEM_BYTES;

    const int tid  = threadIdx.x;
    const int lane = tid & 31;
    const int g    = lane >> 2;
    const int tig  = lane & 3;
    const int w    = tid >> 5;
    const int wy   = w >> 2;        // 0..1 (m, 32 rows each)
    const int wx   = w & 3;         // 0..3 (n, 32 cols each)
    const int rowBase = blockIdx.x * BM;
    const int by = blockIdx.y;

    // ---- load full-K A tile: 64 x 640 fp16 (padded rows, conflict-free) ----
    {
        const __half* gq = g_qh + (size_t)rowBase * D_;
        #pragma unroll
        for (int i = 0; i < 20; ++i) {
            int idx = tid + i * 256;
            int row = idx / 80, kg = idx % 80;
            *(uint4*)(As + row * LDA + kg * 8) =
                *(const uint4*)(gq + (size_t)row * D_ + kg * 8);
        }
    }

    const uint32_t sbA = smem_u32(As);
    const uint32_t sbB = smem_u32(Bs);

    // A ldmatrix per-lane addresses (as before)
    const int aRow = (lane & 7) + ((lane >> 3) & 1) * 8;
    const int aCol = (lane >> 4) * 8;
    uint32_t aAddr[2];
    #pragma unroll
    for (int i = 0; i < 2; ++i)
        aAddr[i] = sbA +
            (uint32_t)(((wy * 32 + i * 16 + aRow) * LDA + aCol) * 2);

    // B ldmatrix per-lane: row-in-16 = ((lane>>4)<<3)+(lane&7), cgoff=(lane>>3)&1
    const int bRowIn = ((lane >> 4) << 3) + (lane & 7);
    const uint32_t cgoff = (lane >> 3) & 1;
    const uint32_t r7 = (uint32_t)(lane & 7);
    uint32_t bRowPart[2];
    #pragma unroll
    for (int L = 0; L < 2; ++L)
        bRowPart[L] = (uint32_t)((wx * 32 + L * 16 + bRowIn) * 128);

    // cp.async: each thread copies 4 x 16B: row = tid&127, cg = (tid>>7)*4+q
    const int cRow = tid & 127;
    const int cgBase = (tid >> 7) * 4;
    const uint32_t cr7 = (uint32_t)(cRow & 7);
    uint32_t cDst[4];
    #pragma unroll
    for (int q = 0; q < 4; ++q)
        cDst[q] = sbB + (uint32_t)(cRow * 128) +
                  ((((uint32_t)(cgBase + q)) ^ cr7) << 4);

    const int ntiles = (NT2 - by + NSTRIPE - 1) / NSTRIPE;
    const int U = ntiles * 10;

    // ---- prologue: chunk 0 into buf 0 ----
    {
        const __half* src = g_rh + ((size_t)(by * BN) + cRow) * D_ + cgBase * 8;
        #pragma unroll
        for (int q = 0; q < 4; ++q)
            cp_async16(cDst[q], src + q * 8);
        CP_COMMIT();
    }
    CP_WAIT0();
    __syncthreads();

    float rm[2][2] = {{-1e30f, -1e30f}, {-1e30f, -1e30f}};
    float acc[2][4][4];

    int nt = by, kt = 0;
    for (int u = 0; u < U; ++u) {
        // issue copy of chunk u+1 into the other buffer
        int kt1 = kt + 1, nt1 = nt;
        if (kt1 == 10) { kt1 = 0; nt1 = nt + NSTRIPE; }
        if (u + 1 < U) {
            const uint32_t bOff = (uint32_t)(((u + 1) & 1) * B_STAGE_BYTES);
            const __half* src =
                g_rh + ((size_t)(nt1 * BN) + cRow) * D_ + kt1 * BK + cgBase * 8;
            #pragma unroll
            for (int q = 0; q < 4; ++q)
                cp_async16(cDst[q] + bOff, src + q * 8);
            CP_COMMIT();
        }

        if (kt == 0) {
            #pragma unroll
            for (int i = 0; i < 2; ++i)
                #pragma unroll
                for (int j = 0; j < 4; ++j)
                    #pragma unroll
                    for (int r = 0; r < 4; ++r) acc[i][j][r] = 0.f;
        }

        // ---- compute chunk u ----
        const uint32_t bufOff = (uint32_t)((u & 1) * B_STAGE_BYTES);
        #pragma unroll
        for (int ks = 0; ks < 4; ++ks) {
            const uint32_t kOffA = (uint32_t)(kt * BK + ks * 16) * 2;
            const uint32_t xoff =
                (((uint32_t)(ks << 1) | cgoff) ^ r7) << 4;
            uint32_t a[2][4], b[2][4];
            ldsm_x4(a[0], aAddr[0] + kOffA);
            ldsm_x4(a[1], aAddr[1] + kOffA);
            ldsm_x4(b[0], sbB + bufOff + bRowPart[0] + xoff);
            ldsm_x4(b[1], sbB + bufOff + bRowPart[1] + xoff);
            #pragma unroll
            for (int i = 0; i < 2; ++i) {
                mma16816(acc[i][0], a[i], &b[0][0]);
                mma16816(acc[i][1], a[i], &b[0][2]);
                mma16816(acc[i][2], a[i], &b[1][0]);
                mma16816(acc[i][3], a[i], &b[1][2]);
            }
        }

        if (kt == 9) {
            const int nBase = nt * BN;
            #pragma unroll
            for (int j = 0; j < 4; ++j) {
                const int c0 = nBase + wx * 32 + j * 8 + tig * 2;
                const bool v0 = (c0 < NR), v1 = (c0 + 1 < NR);
                #pragma unroll
                for (int i = 0; i < 2; ++i) {
                    if (v0) {
                        rm[i][0] = fmaxf(rm[i][0], acc[i][j][0]);
                        rm[i][1] = fmaxf(rm[i][1], acc[i][j][2]);
                    }
                    if (v1) {
                        rm[i][0] = fmaxf(rm[i][0], acc[i][j][1]);
                        rm[i][1] = fmaxf(rm[i][1], acc[i][j][3]);
                    }
                }
            }
        }

        if (u + 1 < U) {
            CP_WAIT0();
            __syncthreads();
        }
        kt = kt1; nt = nt1;
    }

    // ---- reduce: tig lanes, then wx warps via smem (reuse A region) ----
    #pragma unroll
    for (int i = 0; i < 2; ++i)
        #pragma unroll
        for (int s = 0; s < 2; ++s) {
            float v = rm[i][s];
            v = fmaxf(v, __shfl_xor_sync(0xffffffffu, v, 1));
            v = fmaxf(v, __shfl_xor_sync(0xffffffffu, v, 2));
            rm[i][s] = v;
        }
    float* red = (float*)smem;    // A region no longer needed
    __syncthreads();
    if (tig == 0) {
        #pragma unroll
        for (int i = 0; i < 2; ++i)
            #pragma unroll
            for (int s = 0; s < 2; ++s) {
                int row = wy * 32 + i * 16 + s * 8 + g;
                red[row * 5 + wx] = rm[i][s];
            }
    }
    __syncthreads();
    if (tid < BM) {
        float m = red[tid * 5 + 0];
        m = fmaxf(m, red[tid * 5 + 1]);
        m = fmaxf(m, red[tid * 5 + 2]);
        m = fmaxf(m, red[tid * 5 + 3]);
        g_pmax[by * MQ + rowBase + tid] = m;
    }
}

// ---------------------------------------------------------------------------
// Kernel 4a: dr head (side stream; overlaps GEMM). Writes g_sref[b].
// ---------------------------------------------------------------------------
__global__ __launch_bounds__(256)
void heads_dr_kernel(
    const float* __restrict__ q_img,
    const float* __restrict__ dr_w1, const float* __restrict__ dr_b1,
    const float* __restrict__ dr_g2, const float* __restrict__ dr_be2,
    const float* __restrict__ dr_w2, const float* __restrict__ dr_b2,
    const float* __restrict__ dr_g3, const float* __restrict__ dr_be3,
    const float* __restrict__ dr_w3, const float* __restrict__ dr_b3) {
    const int b = blockIdx.x;
    const int t = threadIdx.x;
    __shared__ float xr[D_];
    __shared__ float4 p1[8 * 32];
    __shared__ float p2[256];
    __shared__ float h1[128];
    __shared__ float h2[64];

    for (int i = t; i < D_; i += 256) xr[i] = q_img[b * D_ + i] - g_famean[i];
    __syncthreads();

    {
        const int ng = t & 31, ds = t >> 5;
        const int d0 = ds * 80;
        const float4* wp = (const float4*)dr_w1 + ng;
        float4 buf[8];
        #pragma unroll
        for (int k = 0; k < 8; ++k) buf[k] = wp[(size_t)(d0 + k) * 32];
        float a0 = 0.f, a1 = 0.f, a2 = 0.f, a3 = 0.f;
        #pragma unroll
        for (int bch = 0; bch < 10; ++bch) {
            float4 cur[8];
            #pragma unroll
            for (int k = 0; k < 8; ++k) cur[k] = buf[k];
            if (bch < 9) {
                #pragma unroll
                for (int k = 0; k < 8; ++k)
                    buf[k] = wp[(size_t)(d0 + (bch + 1) * 8 + k) * 32];
            }
            #pragma unroll
            for (int k = 0; k < 8; ++k) {
                const float xv = xr[d0 + bch * 8 + k];
                a0 = fmaf(xv, cur[k].x, a0);
                a1 = fmaf(xv, cur[k].y, a1);
                a2 = fmaf(xv, cur[k].z, a2);
                a3 = fmaf(xv, cur[k].w, a3);
            }
        }
        p1[ds * 32 + ng] = make_float4(a0, a1, a2, a3);
    }
    __syncthreads();
    if (t < 128) {
        const float* p = (const float*)p1;
        float s8 = p[t] + p[128 + t] + p[256 + t] + p[384 + t] +
                   p[512 + t] + p[640 + t] + p[768 + t] + p[896 + t];
        h1[t] = fmaxf(s8 + dr_b1[t], 0.f) * dr_g2[t] + dr_be2[t];
    }
    __syncthreads();
    {
        const int t2 = t & 63, q = t >> 6;
        const int i0 = q * 32;
        const float* wp = dr_w2 + t2;
        float s0 = 0.f, s1 = 0.f;
        #pragma unroll 8
        for (int i = 0; i < 32; i += 2) {
            s0 = fmaf(h1[i0 + i], wp[(size_t)(i0 + i) * 64], s0);
            s1 = fmaf(h1[i0 + i + 1], wp[(size_t)(i0 + i + 1) * 64], s1);
        }
        p2[t] = s0 + s1;
    }
    __syncthreads();
    if (t < 64)
        h2[t] = fmaxf(p2[t] + p2[t + 64] + p2[t + 128] + p2[t + 192] +
                      dr_b2[t], 0.f) * dr_g3[t] + dr_be3[t];
    __syncthreads();
    if (t < 32) {
        float s = h2[t] * dr_w3[t] + h2[t + 32] * dr_w3[t + 32];
        #pragma unroll
        for (int o = 16; o > 0; o >>= 1) s += __shfl_xor_sync(0xffffffffu, s, o);
        if (t == 0) g_sref[b] = 1.f / (1.f + expf(-(s + dr_b3[0])));
    }
}

// ---------------------------------------------------------------------------
// Kernel 4b: dh head + amap mean + final combine (after GEMM).
// ---------------------------------------------------------------------------
__global__ __launch_bounds__(256)
void heads_dh_kernel(
    const float* __restrict__ dh_w1, const float* __restrict__ dh_b1,
    const float* __restrict__ dh_g2, const float* __restrict__ dh_be2,
    const float* __restrict__ dh_w2, const float* __restrict__ dh_b2,
    const float* __restrict__ dh_g3, const float* __restrict__ dh_be3,
    const float* __restrict__ dh_w3, const float* __restrict__ dh_b3,
    float* __restrict__ out) {
    const int b = blockIdx.x;
    const int t = threadIdx.x;
    __shared__ float am[256];
    __shared__ float4 p1[8 * 32];
    __shared__ float p2[256];
    __shared__ float h1[128];
    __shared__ float h2[64];
    __shared__ float s_map_s, mean_s;

    if (t < P_) {
        const int r = b * P_ + t;
        float mx = g_pmax[r];
        mx = fmaxf(mx, g_pmax[MQ + r]);
        mx = fmaxf(mx, g_pmax[2 * MQ + r]);
        mx = fmaxf(mx, g_pmax[3 * MQ + r]);
        am[t] = 0.5f * (1.f - mx / (g_qnorm[r] + 1e-6f));
    } else {
        am[t] = 0.f;
    }
    __syncthreads();

    {
        const int ng = t & 31, ds = t >> 5;
        const int p0 = ds * 32;
        const float4* wp = (const float4*)dh_w1 + ng;
        float4 buf[8];
        #pragma unroll
        for (int k = 0; k < 8; ++k) {
            int p = p0 + k; if (p > 224) p = 224;
            buf[k] = wp[(size_t)p * 32];
        }
        float a0 = 0.f, a1 = 0.f, a2 = 0.f, a3 = 0.f;
        #pragma unroll
        for (int bch = 0; bch < 4; ++bch) {
            float4 cur[8];
            #pragma unroll
            for (int k = 0; k < 8; ++k) cur[k] = buf[k];
            if (bch < 3) {
                #pragma unroll
                for (int k = 0; k < 8; ++k) {
                    int p = p0 + (bch + 1) * 8 + k; if (p > 224) p = 224;
                    buf[k] = wp[(size_t)p * 32];
                }
            }
            #pragma unroll
            for (int k = 0; k < 8; ++k) {
                const float av = am[p0 + bch * 8 + k];
                a0 = fmaf(av, cur[k].x, a0);
                a1 = fmaf(av, cur[k].y, a1);
                a2 = fmaf(av, cur[k].z, a2);
                a3 = fmaf(av, cur[k].w, a3);
            }
        }
        p1[ds * 32 + ng] = make_float4(a0, a1, a2, a3);
    }
    __syncthreads();
    if (t < 128) {
        const float* p = (const float*)p1;
        float s8 = p[t] + p[128 + t] + p[256 + t] + p[384 + t] +
                   p[512 + t] + p[640 + t] + p[768 + t] + p[896 + t];
        h1[t] = fmaxf(s8 + dh_b1[t], 0.f) * dh_g2[t] + dh_be2[t];
    } else {
        const int tt = t - 128;
        if (tt < 32) {
            float s = 0.f;
            #pragma unroll
            for (int j = 0; j < 8; ++j) s += am[tt + 32 * j];
            #pragma unroll
            for (int o = 16; o > 0; o >>= 1)
                s += __shfl_xor_sync(0xffffffffu, s, o);
            if (tt == 0) mean_s = s * (1.f / (float)P_);
        }
    }
    __syncthreads();
    {
        const int t2 = t & 63, q = t >> 6;
        const int i0 = q * 32;
        const float* wp = dh_w2 + t2;
        float s0 = 0.f, s1 = 0.f;
        #pragma unroll 8
        for (int i = 0; i < 32; i += 2) {
            s0 = fmaf(h1[i0 + i], wp[(size_t)(i0 + i) * 64], s0);
            s1 = fmaf(h1[i0 + i + 1], wp[(size_t)(i0 + i + 1) * 64], s1);
        }
        p2[t] = s0 + s1;
    }
    __syncthreads();
    if (t < 64)
        h2[t] = fmaxf(p2[t] + p2[t + 64] + p2[t + 128] + p2[t + 192] +
                      dh_b2[t], 0.f) * dh_g3[t] + dh_be3[t];
    __syncthreads();
    if (t < 32) {
        float s = h2[t] * dh_w3[t] + h2[t + 32] * dh_w3[t + 32];
        #pragma unroll
        for (int o = 16; o > 0; o >>= 1) s += __shfl_xor_sync(0xffffffffu, s, o);
        if (t == 0) {
            s_map_s = 1.f / (1.f + expf(-(s + dh_b3[0])));
            out[b] = 0.5f * (g_sref[b] + s_map_s) + mean_s;
        }
    }
}

// ---------------------------------------------------------------------------
// Launch: fork adapter+dr-head onto a side stream, overlapping the GEMM.
// ---------------------------------------------------------------------------
extern "C" void kernel_launch(void* const* d_in, const int* in_sizes, int n_in,
                              void* d_out, int out_size) {
    const float* q_patch = (const float*)d_in[0];
    const float* r_patch = (const float*)d_in[1];
    const float* q_img   = (const float*)d_in[2];
    const float* r_img   = (const float*)d_in[3];
    const float* adpt_w1 = (const float*)d_in[4];
    const float* adpt_w2 = (const float*)d_in[5];
    const float* dh_w1  = (const float*)d_in[6];
    const float* dh_b1  = (const float*)d_in[7];
    const float* dh_g2  = (const float*)d_in[8];
    const float* dh_be2 = (const float*)d_in[9];
    const float* dh_w2  = (const float*)d_in[10];
    const float* dh_b2  = (const float*)d_in[11];
    const float* dh_g3  = (const float*)d_in[12];
    const float* dh_be3 = (const float*)d_in[13];
    const float* dh_w3  = (const float*)d_in[14];
    const float* dh_b3  = (const float*)d_in[15];
    const float* dr_w1  = (const float*)d_in[16];
    const float* dr_b1  = (const float*)d_in[17];
    const float* dr_g2  = (const float*)d_in[18];
    const float* dr_be2 = (const float*)d_in[19];
    const float* dr_w2  = (const float*)d_in[20];
    const float* dr_b2  = (const float*)d_in[21];
    const float* dr_g3  = (const float*)d_in[22];
    const float* dr_be3 = (const float*)d_in[23];
    const float* dr_w3  = (const float*)d_in[24];
    const float* dr_b3  = (const float*)d_in[25];
    float* out = (float*)d_out;

    static cudaStream_t s2 = nullptr;
    static cudaEvent_t evFork = nullptr, evJoin = nullptr;
    if (s2 == nullptr) {
        cudaFuncSetAttribute(gemm_max_kernel,
                             cudaFuncAttributeMaxDynamicSharedMemorySize,
                             SMEM_BYTES);
        cudaStreamCreateWithFlags(&s2, cudaStreamNonBlocking);
        cudaEventCreateWithFlags(&evFork, cudaEventDisableTiming);
        cudaEventCreateWithFlags(&evJoin, cudaEventDisableTiming);
    }

    mega_prep_kernel<<<PREP_BLOCKS, 512>>>(q_patch, r_patch, r_img, adpt_w1);

    cudaEventRecord(evFork, 0);
    cudaStreamWaitEvent(s2, evFork, 0);
    adapter_final_kernel<<<D_ / 128, 128, 0, s2>>>(adpt_w2);
    heads_dr_kernel<<<B_, 256, 0, s2>>>(q_img,
                                        dr_w1, dr_b1, dr_g2, dr_be2,
                                        dr_w2, dr_b2, dr_g3, dr_be3,
                                        dr_w3, dr_b3);
    cudaEventRecord(evJoin, s2);

    gemm_max_kernel<<<dim3(MQ / BM, NSTRIPE), 256, SMEM_BYTES>>>();

    cudaStreamWaitEvent(0, evJoin, 0);
    heads_dh_kernel<<<B_, 256>>>(dh_w1, dh_b1, dh_g2, dh_be2,
                                 dh_w2, dh_b2, dh_g3, dh_be3,
                                 dh_w3, dh_b3, out);
}

// round 16
// speedup vs baseline: 1.7761x; 1.7761x over previous
#include <cuda_runtime.h>
#include <cuda_fp16.h>
#include <math.h>
#include <stdint.h>

// ---------------------------------------------------------------------------
// Problem constants
// ---------------------------------------------------------------------------
#define B_   64
#define P_   225
#define K_   16
#define D_   640
#define MQ   (B_ * P_)      // 14400 query rows
#define NR   (K_ * P_)      // 3600 reference rows
#define NT2  29             // n tiles of 128
#define NRP  (NT2 * 128)    // 3712 padded reference rows

// GEMM tiling: BM=64, BN=128, BK=64; 8 warps (2m x 4n), warp tile 32x32
#define BM 64
#define BN 128
#define BK 64
#define LDA 648             // A smem row stride (fp16); row stride = 4 banks
#define NSTRIPE 4
#define NSTAGE 2
#define B_STAGE_BYTES (BN * 128)                    // 16384 (swizzled, no pad)

#define A_SMEM_BYTES (BM * LDA * 2)                 // 82944
#define SMEM_BYTES   (A_SMEM_BYTES + NSTAGE * B_STAGE_BYTES)  // 115712

// prep: 16 rows per 512-thread block (warp per row) + adapter tail blocks
#define ROWBLKS ((MQ + NRP) / 16)                   // 1132
#define ADPT_BLKS 20
#define PREP_BLOCKS (ROWBLKS + ADPT_BLKS)

// ---------------------------------------------------------------------------
// Scratch (allocation-free: __device__ globals)
// ---------------------------------------------------------------------------
__device__ __half g_qh[MQ * D_];
__device__ __half g_rh[NRP * D_];
__device__ float g_qnorm[MQ];
__device__ float g_pmax[NSTRIPE * MQ];
__device__ float g_h1p[5][K_ * 160];
__device__ float g_famean[D_];
__device__ float g_sref[B_];

// ---------------------------------------------------------------------------
// helpers
// ---------------------------------------------------------------------------
__device__ __forceinline__ uint32_t smem_u32(const void* p) {
    uint32_t a;
    asm("{ .reg .u64 t; cvta.to.shared.u64 t, %1; cvt.u32.u64 %0, t; }"
        : "=r"(a) : "l"(p));
    return a;
}
__device__ __forceinline__ void cp_async16(uint32_t dst, const void* src) {
    asm volatile("cp.async.cg.shared.global [%0], [%1], 16;"
                 :: "r"(dst), "l"(src) : "memory");
}
#define CP_COMMIT() asm volatile("cp.async.commit_group;" ::: "memory")
#define CP_WAIT0()  asm volatile("cp.async.wait_group 0;" ::: "memory")

__device__ __forceinline__ void ldsm_x4(uint32_t r[4], uint32_t addr) {
    asm volatile("ldmatrix.sync.aligned.m8n8.x4.shared.b16 {%0,%1,%2,%3}, [%4];"
                 : "=r"(r[0]), "=r"(r[1]), "=r"(r[2]), "=r"(r[3]) : "r"(addr));
}
__device__ __forceinline__ void mma16816(float c[4], const uint32_t a[4],
                                         const uint32_t b[2]) {
    asm volatile(
        "mma.sync.aligned.m16n8k16.row.col.f32.f16.f16.f32 "
        "{%0,%1,%2,%3}, {%4,%5,%6,%7}, {%8,%9}, {%0,%1,%2,%3};\n"
        : "+f"(c[0]), "+f"(c[1]), "+f"(c[2]), "+f"(c[3])
        : "r"(a[0]), "r"(a[1]), "r"(a[2]), "r"(a[3]), "r"(b[0]), "r"(b[1]));
}

// ---------------------------------------------------------------------------
// Kernel 1 (fused prep): warp-per-row q/r prep + adapter hidden partials
// ---------------------------------------------------------------------------
__global__ __launch_bounds__(512)
void mega_prep_kernel(const float* __restrict__ q_patch,
                      const float* __restrict__ r_patch,
                      const float* __restrict__ r_img,
                      const float* __restrict__ w1) {
    const int t = threadIdx.x;

    if (blockIdx.x < ROWBLKS) {
        const int lane = t & 31;
        const int row = blockIdx.x * 16 + (t >> 5);
        if (row < MQ) {
            const float4* x4 = (const float4*)(q_patch + (size_t)row * D_);
            __half* o = g_qh + (size_t)row * D_;
            float4 v[5];
            float ss = 0.f;
            #pragma unroll
            for (int j = 0; j < 5; ++j) {
                const int i4 = lane + 32 * j;
                v[j] = x4[i4];
                ss = fmaf(v[j].x, v[j].x, ss);
                ss = fmaf(v[j].y, v[j].y, ss);
                ss = fmaf(v[j].z, v[j].z, ss);
                ss = fmaf(v[j].w, v[j].w, ss);
                *(__half2*)(o + i4 * 4)     = __floats2half2_rn(v[j].x, v[j].y);
                *(__half2*)(o + i4 * 4 + 2) = __floats2half2_rn(v[j].z, v[j].w);
            }
            #pragma unroll
            for (int of = 16; of > 0; of >>= 1)
                ss += __shfl_xor_sync(0xffffffffu, ss, of);
            if (lane == 0) g_qnorm[row] = sqrtf(ss);
        } else {
            const int r = row - MQ;
            __half* o = g_rh + (size_t)r * D_;
            if (r >= NR) {
                #pragma unroll
                for (int j = 0; j < 5; ++j) {
                    const int i4 = lane + 32 * j;
                    *(__half2*)(o + i4 * 4)     = __floats2half2_rn(0.f, 0.f);
                    *(__half2*)(o + i4 * 4 + 2) = __floats2half2_rn(0.f, 0.f);
                }
            } else {
                const float4* x4 = (const float4*)(r_patch + (size_t)r * D_);
                float4 v[5];
                float ss = 0.f;
                #pragma unroll
                for (int j = 0; j < 5; ++j) {
                    v[j] = x4[lane + 32 * j];
                    ss = fmaf(v[j].x, v[j].x, ss);
                    ss = fmaf(v[j].y, v[j].y, ss);
                    ss = fmaf(v[j].z, v[j].z, ss);
                    ss = fmaf(v[j].w, v[j].w, ss);
                }
                #pragma unroll
                for (int of = 16; of > 0; of >>= 1)
                    ss += __shfl_xor_sync(0xffffffffu, ss, of);
                const float sc = 1.f / (sqrtf(ss) + 1e-6f);
                #pragma unroll
                for (int j = 0; j < 5; ++j) {
                    const int i4 = lane + 32 * j;
                    *(__half2*)(o + i4 * 4) =
                        __floats2half2_rn(v[j].x * sc, v[j].y * sc);
                    *(__half2*)(o + i4 * 4 + 2) =
                        __floats2half2_rn(v[j].z * sc, v[j].w * sc);
                }
            }
        }
    } else {
        const int grp = t >> 7;
        const int tg = t & 127;
        const int idx = (blockIdx.x - ROWBLKS) * 4 + grp;
        const int k = idx / 5, dc = idx % 5;
        __shared__ float axr[4][128];
        axr[grp][tg] = r_img[k * D_ + dc * 128 + tg];
        __syncthreads();
        const float* xr = axr[grp];
        #pragma unroll
        for (int rep = 0; rep < 2; ++rep) {
            const int i = tg + rep * 128;
            if (i < 160) {
                float s0 = 0.f, s1 = 0.f;
                const float* w = w1 + (size_t)(dc * 128) * 160 + i;
                #pragma unroll 8
                for (int d = 0; d < 128; d += 2) {
                    s0 = fmaf(xr[d], w[(size_t)d * 160], s0);
                    s1 = fmaf(xr[d + 1], w[(size_t)(d + 1) * 160], s1);
                }
                g_h1p[dc][k * 160 + i] = s0 + s1;
            }
        }
    }
}

// ---------------------------------------------------------------------------
// Kernel 2: adapter finish
// ---------------------------------------------------------------------------
__global__ void adapter_final_kernel(const float* __restrict__ w2) {
    __shared__ float h1s[K_ * 160];
    for (int idx = threadIdx.x; idx < K_ * 160; idx += 128) {
        float s = g_h1p[0][idx] + g_h1p[1][idx] + g_h1p[2][idx] +
                  g_h1p[3][idx] + g_h1p[4][idx];
        h1s[idx] = fmaxf(s, 0.f);
    }
    __syncthreads();
    const int j = blockIdx.x * 128 + threadIdx.x;
    float accm = 0.f;
    for (int k = 0; k < K_; ++k) {
        float s0 = 0.f, s1 = 0.f;
        const float* h = h1s + k * 160;
        #pragma unroll 4
        for (int i = 0; i < 160; i += 2) {
            s0 = fmaf(h[i], w2[i * D_ + j], s0);
            s1 = fmaf(h[i + 1], w2[(i + 1) * D_ + j], s1);
        }
        accm += fmaxf(s0 + s1, 0.f);
    }
    g_famean[j] = accm * (1.f / (float)K_);
}

// ---------------------------------------------------------------------------
// Kernel 3: tensor-core GEMM + row max. BN=128, swizzled B, ldsm_x4 B frags.
// cp.async remapped for full-line coalescing (8 lanes = 128B of one row).
// ---------------------------------------------------------------------------
__global__ __launch_bounds__(256, 2)
void gemm_max_kernel() {
    extern __shared__ __align__(16) char smem[];
    __half* As = (__half*)smem;
    char* Bs = smem + A_SMEM_BYTES;

    const int tid  = threadIdx.x;
    const int lane = tid & 31;
    const int g    = lane >> 2;
    const int tig  = lane & 3;
    const int w    = tid >> 5;
    const int wy   = w >> 2;        // 0..1 (m, 32 rows each)
    const int wx   = w & 3;         // 0..3 (n, 32 cols each)
    const int rowBase = blockIdx.x * BM;
    const int by = blockIdx.y;

    // ---- load full-K A tile: 64 x 640 fp16 (padded rows, conflict-free) ----
    {
        const __half* gq = g_qh + (size_t)rowBase * D_;
        #pragma unroll
        for (int i = 0; i < 20; ++i) {
            int idx = tid + i * 256;
            int row = idx / 80, kg = idx % 80;
            *(uint4*)(As + row * LDA + kg * 8) =
                *(const uint4*)(gq + (size_t)row * D_ + kg * 8);
        }
    }

    const uint32_t sbA = smem_u32(As);
    const uint32_t sbB = smem_u32(Bs);

    // A ldmatrix per-lane addresses
    const int aRow = (lane & 7) + ((lane >> 3) & 1) * 8;
    const int aCol = (lane >> 4) * 8;
    uint32_t aAddr[2];
    #pragma unroll
    for (int i = 0; i < 2; ++i)
        aAddr[i] = sbA +
            (uint32_t)(((wy * 32 + i * 16 + aRow) * LDA + aCol) * 2);

    // B ldmatrix per-lane: row-in-16 = ((lane>>4)<<3)+(lane&7), cgoff=(lane>>3)&1
    const int bRowIn = ((lane >> 4) << 3) + (lane & 7);
    const uint32_t cgoff = (lane >> 3) & 1;
    const uint32_t r7 = (uint32_t)(lane & 7);
    uint32_t bRowPart[2];
    #pragma unroll
    for (int L = 0; L < 2; ++L)
        bRowPart[L] = (uint32_t)((wx * 32 + L * 16 + bRowIn) * 128);

    // cp.async: COALESCED mapping. base row = tid>>3 (0..31), group = tid&7;
    // thread copies rows base+32q, q=0..3, same 16B group. Each warp
    // instruction covers 4 full contiguous 128B lines.
    const int cRow = tid >> 3;          // 0..31
    const int cg   = tid & 7;
    const uint32_t cr7 = (uint32_t)(cRow & 7);   // (cRow+32q)&7 == cRow&7
    const uint32_t cSw = (((uint32_t)cg ^ cr7) << 4);
    uint32_t cDst[4];
    #pragma unroll
    for (int q = 0; q < 4; ++q)
        cDst[q] = sbB + (uint32_t)((cRow + 32 * q) * 128) + cSw;
    const __half* cSrcBase = g_rh + (size_t)cRow * D_ + cg * 8;

    const int ntiles = (NT2 - by + NSTRIPE - 1) / NSTRIPE;
    const int U = ntiles * 10;

    // ---- prologue: chunk 0 into buf 0 ----
    {
        const __half* src = cSrcBase + (size_t)(by * BN) * D_;
        #pragma unroll
        for (int q = 0; q < 4; ++q)
            cp_async16(cDst[q], src + (size_t)(32 * q) * D_);
        CP_COMMIT();
    }
    CP_WAIT0();
    __syncthreads();

    float rm[2][2] = {{-1e30f, -1e30f}, {-1e30f, -1e30f}};
    float acc[2][4][4];

    int nt = by, kt = 0;
    for (int u = 0; u < U; ++u) {
        // issue copy of chunk u+1 into the other buffer
        int kt1 = kt + 1, nt1 = nt;
        if (kt1 == 10) { kt1 = 0; nt1 = nt + NSTRIPE; }
        if (u + 1 < U) {
            const uint32_t bOff = (uint32_t)(((u + 1) & 1) * B_STAGE_BYTES);
            const __half* src =
                cSrcBase + (size_t)(nt1 * BN) * D_ + kt1 * BK;
            #pragma unroll
            for (int q = 0; q < 4; ++q)
                cp_async16(cDst[q] + bOff, src + (size_t)(32 * q) * D_);
            CP_COMMIT();
        }

        if (kt == 0) {
            #pragma unroll
            for (int i = 0; i < 2; ++i)
                #pragma unroll
                for (int j = 0; j < 4; ++j)
                    #pragma unroll
                    for (int r = 0; r < 4; ++r) acc[i][j][r] = 0.f;
        }

        // ---- compute chunk u ----
        const uint32_t bufOff = (uint32_t)((u & 1) * B_STAGE_BYTES);
        #pragma unroll
        for (int ks = 0; ks < 4; ++ks) {
            const uint32_t kOffA = (uint32_t)(kt * BK + ks * 16) * 2;
            const uint32_t xoff =
                (((uint32_t)(ks << 1) | cgoff) ^ r7) << 4;
            uint32_t a[2][4], b[2][4];
            ldsm_x4(a[0], aAddr[0] + kOffA);
            ldsm_x4(a[1], aAddr[1] + kOffA);
            ldsm_x4(b[0], sbB + bufOff + bRowPart[0] + xoff);
            ldsm_x4(b[1], sbB + bufOff + bRowPart[1] + xoff);
            #pragma unroll
            for (int i = 0; i < 2; ++i) {
                mma16816(acc[i][0], a[i], &b[0][0]);
                mma16816(acc[i][1], a[i], &b[0][2]);
                mma16816(acc[i][2], a[i], &b[1][0]);
                mma16816(acc[i][3], a[i], &b[1][2]);
            }
        }

        if (kt == 9) {
            const int nBase = nt * BN;
            #pragma unroll
            for (int j = 0; j < 4; ++j) {
                const int c0 = nBase + wx * 32 + j * 8 + tig * 2;
                const bool v0 = (c0 < NR), v1 = (c0 + 1 < NR);
                #pragma unroll
                for (int i = 0; i < 2; ++i) {
                    if (v0) {
                        rm[i][0] = fmaxf(rm[i][0], acc[i][j][0]);
                        rm[i][1] = fmaxf(rm[i][1], acc[i][j][2]);
                    }
                    if (v1) {
                        rm[i][0] = fmaxf(rm[i][0], acc[i][j][1]);
                        rm[i][1] = fmaxf(rm[i][1], acc[i][j][3]);
                    }
                }
            }
        }

        if (u + 1 < U) {
            CP_WAIT0();
            __syncthreads();
        }
        kt = kt1; nt = nt1;
    }

    // ---- reduce: tig lanes, then wx warps via smem (reuse A region) ----
    #pragma unroll
    for (int i = 0; i < 2; ++i)
        #pragma unroll
        for (int s = 0; s < 2; ++s) {
            float v = rm[i][s];
            v = fmaxf(v, __shfl_xor_sync(0xffffffffu, v, 1));
            v = fmaxf(v, __shfl_xor_sync(0xffffffffu, v, 2));
            rm[i][s] = v;
        }
    float* red = (float*)smem;    // A region no longer needed
    __syncthreads();
    if (tig == 0) {
        #pragma unroll
        for (int i = 0; i < 2; ++i)
            #pragma unroll
            for (int s = 0; s < 2; ++s) {
                int row = wy * 32 + i * 16 + s * 8 + g;
                red[row * 5 + wx] = rm[i][s];
            }
    }
    __syncthreads();
    if (tid < BM) {
        float m = red[tid * 5 + 0];
        m = fmaxf(m, red[tid * 5 + 1]);
        m = fmaxf(m, red[tid * 5 + 2]);
        m = fmaxf(m, red[tid * 5 + 3]);
        g_pmax[by * MQ + rowBase + tid] = m;
    }
}

// ---------------------------------------------------------------------------
// Kernel 4a: dr head (side stream; overlaps GEMM). Writes g_sref[b].
// ---------------------------------------------------------------------------
__global__ __launch_bounds__(256)
void heads_dr_kernel(
    const float* __restrict__ q_img,
    const float* __restrict__ dr_w1, const float* __restrict__ dr_b1,
    const float* __restrict__ dr_g2, const float* __restrict__ dr_be2,
    const float* __restrict__ dr_w2, const float* __restrict__ dr_b2,
    const float* __restrict__ dr_g3, const float* __restrict__ dr_be3,
    const float* __restrict__ dr_w3, const float* __restrict__ dr_b3) {
    const int b = blockIdx.x;
    const int t = threadIdx.x;
    __shared__ float xr[D_];
    __shared__ float4 p1[8 * 32];
    __shared__ float p2[256];
    __shared__ float h1[128];
    __shared__ float h2[64];

    for (int i = t; i < D_; i += 256) xr[i] = q_img[b * D_ + i] - g_famean[i];
    __syncthreads();

    {
        const int ng = t & 31, ds = t >> 5;
        const int d0 = ds * 80;
        const float4* wp = (const float4*)dr_w1 + ng;
        float4 buf[8];
        #pragma unroll
        for (int k = 0; k < 8; ++k) buf[k] = wp[(size_t)(d0 + k) * 32];
        float a0 = 0.f, a1 = 0.f, a2 = 0.f, a3 = 0.f;
        #pragma unroll
        for (int bch = 0; bch < 10; ++bch) {
            float4 cur[8];
            #pragma unroll
            for (int k = 0; k < 8; ++k) cur[k] = buf[k];
            if (bch < 9) {
                #pragma unroll
                for (int k = 0; k < 8; ++k)
                    buf[k] = wp[(size_t)(d0 + (bch + 1) * 8 + k) * 32];
            }
            #pragma unroll
            for (int k = 0; k < 8; ++k) {
                const float xv = xr[d0 + bch * 8 + k];
                a0 = fmaf(xv, cur[k].x, a0);
                a1 = fmaf(xv, cur[k].y, a1);
                a2 = fmaf(xv, cur[k].z, a2);
                a3 = fmaf(xv, cur[k].w, a3);
            }
        }
        p1[ds * 32 + ng] = make_float4(a0, a1, a2, a3);
    }
    __syncthreads();
    if (t < 128) {
        const float* p = (const float*)p1;
        float s8 = p[t] + p[128 + t] + p[256 + t] + p[384 + t] +
                   p[512 + t] + p[640 + t] + p[768 + t] + p[896 + t];
        h1[t] = fmaxf(s8 + dr_b1[t], 0.f) * dr_g2[t] + dr_be2[t];
    }
    __syncthreads();
    {
        const int t2 = t & 63, q = t >> 6;
        const int i0 = q * 32;
        const float* wp = dr_w2 + t2;
        float s0 = 0.f, s1 = 0.f;
        #pragma unroll 8
        for (int i = 0; i < 32; i += 2) {
            s0 = fmaf(h1[i0 + i], wp[(size_t)(i0 + i) * 64], s0);
            s1 = fmaf(h1[i0 + i + 1], wp[(size_t)(i0 + i + 1) * 64], s1);
        }
        p2[t] = s0 + s1;
    }
    __syncthreads();
    if (t < 64)
        h2[t] = fmaxf(p2[t] + p2[t + 64] + p2[t + 128] + p2[t + 192] +
                      dr_b2[t], 0.f) * dr_g3[t] + dr_be3[t];
    __syncthreads();
    if (t < 32) {
        float s = h2[t] * dr_w3[t] + h2[t + 32] * dr_w3[t + 32];
        #pragma unroll
        for (int o = 16; o > 0; o >>= 1) s += __shfl_xor_sync(0xffffffffu, s, o);
        if (t == 0) g_sref[b] = 1.f / (1.f + expf(-(s + dr_b3[0])));
    }
}

// ---------------------------------------------------------------------------
// Kernel 4b: dh head + amap mean + final combine (after GEMM).
// ---------------------------------------------------------------------------
__global__ __launch_bounds__(256)
void heads_dh_kernel(
    const float* __restrict__ dh_w1, const float* __restrict__ dh_b1,
    const float* __restrict__ dh_g2, const float* __restrict__ dh_be2,
    const float* __restrict__ dh_w2, const float* __restrict__ dh_b2,
    const float* __restrict__ dh_g3, const float* __restrict__ dh_be3,
    const float* __restrict__ dh_w3, const float* __restrict__ dh_b3,
    float* __restrict__ out) {
    const int b = blockIdx.x;
    const int t = threadIdx.x;
    __shared__ float am[256];
    __shared__ float4 p1[8 * 32];
    __shared__ float p2[256];
    __shared__ float h1[128];
    __shared__ float h2[64];
    __shared__ float s_map_s, mean_s;

    if (t < P_) {
        const int r = b * P_ + t;
        float mx = g_pmax[r];
        mx = fmaxf(mx, g_pmax[MQ + r]);
        mx = fmaxf(mx, g_pmax[2 * MQ + r]);
        mx = fmaxf(mx, g_pmax[3 * MQ + r]);
        am[t] = 0.5f * (1.f - mx / (g_qnorm[r] + 1e-6f));
    } else {
        am[t] = 0.f;
    }
    __syncthreads();

    {
        const int ng = t & 31, ds = t >> 5;
        const int p0 = ds * 32;
        const float4* wp = (const float4*)dh_w1 + ng;
        float4 buf[8];
        #pragma unroll
        for (int k = 0; k < 8; ++k) {
            int p = p0 + k; if (p > 224) p = 224;
            buf[k] = wp[(size_t)p * 32];
        }
        float a0 = 0.f, a1 = 0.f, a2 = 0.f, a3 = 0.f;
        #pragma unroll
        for (int bch = 0; bch < 4; ++bch) {
            float4 cur[8];
            #pragma unroll
            for (int k = 0; k < 8; ++k) cur[k] = buf[k];
            if (bch < 3) {
                #pragma unroll
                for (int k = 0; k < 8; ++k) {
                    int p = p0 + (bch + 1) * 8 + k; if (p > 224) p = 224;
                    buf[k] = wp[(size_t)p * 32];
                }
            }
            #pragma unroll
            for (int k = 0; k < 8; ++k) {
                const float av = am[p0 + bch * 8 + k];
                a0 = fmaf(av, cur[k].x, a0);
                a1 = fmaf(av, cur[k].y, a1);
                a2 = fmaf(av, cur[k].z, a2);
                a3 = fmaf(av, cur[k].w, a3);
            }
        }
        p1[ds * 32 + ng] = make_float4(a0, a1, a2, a3);
    }
    __syncthreads();
    if (t < 128) {
        const float* p = (const float*)p1;
        float s8 = p[t] + p[128 + t] + p[256 + t] + p[384 + t] +
                   p[512 + t] + p[640 + t] + p[768 + t] + p[896 + t];
        h1[t] = fmaxf(s8 + dh_b1[t], 0.f) * dh_g2[t] + dh_be2[t];
    } else {
        const int tt = t - 128;
        if (tt < 32) {
            float s = 0.f;
            #pragma unroll
            for (int j = 0; j < 8; ++j) s += am[tt + 32 * j];
            #pragma unroll
            for (int o = 16; o > 0; o >>= 1)
                s += __shfl_xor_sync(0xffffffffu, s, o);
            if (tt == 0) mean_s = s * (1.f / (float)P_);
        }
    }
    __syncthreads();
    {
        const int t2 = t & 63, q = t >> 6;
        const int i0 = q * 32;
        const float* wp = dh_w2 + t2;
        float s0 = 0.f, s1 = 0.f;
        #pragma unroll 8
        for (int i = 0; i < 32; i += 2) {
            s0 = fmaf(h1[i0 + i], wp[(size_t)(i0 + i) * 64], s0);
            s1 = fmaf(h1[i0 + i + 1], wp[(size_t)(i0 + i + 1) * 64], s1);
        }
        p2[t] = s0 + s1;
    }
    __syncthreads();
    if (t < 64)
        h2[t] = fmaxf(p2[t] + p2[t + 64] + p2[t + 128] + p2[t + 192] +
                      dh_b2[t], 0.f) * dh_g3[t] + dh_be3[t];
    __syncthreads();
    if (t < 32) {
        float s = h2[t] * dh_w3[t] + h2[t + 32] * dh_w3[t + 32];
        #pragma unroll
        for (int o = 16; o > 0; o >>= 1) s += __shfl_xor_sync(0xffffffffu, s, o);
        if (t == 0) {
            s_map_s = 1.f / (1.f + expf(-(s + dh_b3[0])));
            out[b] = 0.5f * (g_sref[b] + s_map_s) + mean_s;
        }
    }
}

// ---------------------------------------------------------------------------
// Launch: fork adapter+dr-head onto a side stream, overlapping the GEMM.
// ---------------------------------------------------------------------------
extern "C" void kernel_launch(void* const* d_in, const int* in_sizes, int n_in,
                              void* d_out, int out_size) {
    const float* q_patch = (const float*)d_in[0];
    const float* r_patch = (const float*)d_in[1];
    const float* q_img   = (const float*)d_in[2];
    const float* r_img   = (const float*)d_in[3];
    const float* adpt_w1 = (const float*)d_in[4];
    const float* adpt_w2 = (const float*)d_in[5];
    const float* dh_w1  = (const float*)d_in[6];
    const float* dh_b1  = (const float*)d_in[7];
    const float* dh_g2  = (const float*)d_in[8];
    const float* dh_be2 = (const float*)d_in[9];
    const float* dh_w2  = (const float*)d_in[10];
    const float* dh_b2  = (const float*)d_in[11];
    const float* dh_g3  = (const float*)d_in[12];
    const float* dh_be3 = (const float*)d_in[13];
    const float* dh_w3  = (const float*)d_in[14];
    const float* dh_b3  = (const float*)d_in[15];
    const float* dr_w1  = (const float*)d_in[16];
    const float* dr_b1  = (const float*)d_in[17];
    const float* dr_g2  = (const float*)d_in[18];
    const float* dr_be2 = (const float*)d_in[19];
    const float* dr_w2  = (const float*)d_in[20];
    const float* dr_b2  = (const float*)d_in[21];
    const float* dr_g3  = (const float*)d_in[22];
    const float* dr_be3 = (const float*)d_in[23];
    const float* dr_w3  = (const float*)d_in[24];
    const float* dr_b3  = (const float*)d_in[25];
    float* out = (float*)d_out;

    static cudaStream_t s2 = nullptr;
    static cudaEvent_t evFork = nullptr, evJoin = nullptr;
    if (s2 == nullptr) {
        cudaFuncSetAttribute(gemm_max_kernel,
                             cudaFuncAttributeMaxDynamicSharedMemorySize,
                             SMEM_BYTES);
        cudaStreamCreateWithFlags(&s2, cudaStreamNonBlocking);
        cudaEventCreateWithFlags(&evFork, cudaEventDisableTiming);
        cudaEventCreateWithFlags(&evJoin, cudaEventDisableTiming);
    }

    mega_prep_kernel<<<PREP_BLOCKS, 512>>>(q_patch, r_patch, r_img, adpt_w1);

    cudaEventRecord(evFork, 0);
    cudaStreamWaitEvent(s2, evFork, 0);
    adapter_final_kernel<<<D_ / 128, 128, 0, s2>>>(adpt_w2);
    heads_dr_kernel<<<B_, 256, 0, s2>>>(q_img,
                                        dr_w1, dr_b1, dr_g2, dr_be2,
                                        dr_w2, dr_b2, dr_g3, dr_be3,
                                        dr_w3, dr_b3);
    cudaEventRecord(evJoin, s2);

    gemm_max_kernel<<<dim3(MQ / BM, NSTRIPE), 256, SMEM_BYTES>>>();

    cudaStreamWaitEvent(0, evJoin, 0);
    heads_dh_kernel<<<B_, 256>>>(dh_w1, dh_b1, dh_g2, dh_be2,
                                 dh_w2, dh_b2, dh_g3, dh_be3,
                                 dh_w3, dh_b3, out);
}